// round 10
// baseline (speedup 1.0000x reference)
#include <cuda_runtime.h>
#include <cuda_fp16.h>
#include <cstdint>
#include <math.h>

#define BATCH 2
#define CT 64      // thermal channels (= output channels)
#define CO 32      // optical channels (= V dim)
#define ED 64      // embed dim E
#define HI 32
#define WI 32
#define HO 96
#define WO 96
#define NQ (HO*WO)     // 9216
#define QB 128         // queries per CTA
#define KT 64          // keys per smem tile
#define NSPLIT 3       // key-dimension split
#define NT2 (NQ/KT/NSPLIT)   // 48 tiles per CTA
#define NQB (NQ/QB)    // 72 query blocks
#define QSCALE 0.180336880f   // (1/sqrt(64)) * log2(e): softmax becomes exp2(s)
#define ONES2 0x3C003C00u     // f16x2 {1.0, 1.0}
#define PSTRIDE 36     // padded row: 32 num + den@32 + pad (144B, 16B aligned)
#define NBUF 3         // K/V smem ring depth

// dynamic smem layout (61440 B total) -> 3 CTAs/SM
#define SM_Q   0                      // [128][144B]
#define SM_K   18432                  // 3 x [64 rows][144B]
#define SM_V   46080                  // 3 x [64 rows][80B]
#define SM_TOTAL 61440
// epilogue overlays
#define SM_OSM 0                      // [128][36] f32
#define SM_WSM 18432                  // [64][32] f32
#define SM_BNA 26624
#define SM_BNB 26880

#define ZSTRIDE ((size_t)BATCH*NQB*QB*PSTRIDE)

// scratch (allocation-free: __device__ globals)
__device__ __half g_qh[BATCH*NQ*ED];   // [b][n][e], pre-scaled by QSCALE
__device__ __half g_kh[BATCH*NQ*ED];   // [b][m][e]
__device__ __half g_vh[BATCH*NQ*CO];   // [b][m][o]
__device__ float  g_part[NSPLIT*BATCH*NQB*QB*PSTRIDE];  // split-K partials
__device__ int    g_sync[BATCH*NQB];   // per-qblock arrival counters

// ---------------------------------------------------------------------------
// helpers
// ---------------------------------------------------------------------------
__device__ __forceinline__ uint32_t pack2(float a, float b) {
    __half2 h = __floats2half2_rn(a, b);
    return *(uint32_t*)&h;
}
__device__ __forceinline__ uint32_t h2ex2(uint32_t x) {
    uint32_t y; asm("ex2.approx.f16x2 %0, %1;" : "=r"(y) : "r"(x)); return y;
}
__device__ __forceinline__ void ldsm4(uint32_t* r, uint32_t addr) {
    asm volatile("ldmatrix.sync.aligned.m8n8.x4.shared.b16 {%0,%1,%2,%3}, [%4];"
        : "=r"(r[0]), "=r"(r[1]), "=r"(r[2]), "=r"(r[3]) : "r"(addr));
}
__device__ __forceinline__ void ldsm4t(uint32_t* r, uint32_t addr) {
    asm volatile("ldmatrix.sync.aligned.m8n8.x4.trans.shared.b16 {%0,%1,%2,%3}, [%4];"
        : "=r"(r[0]), "=r"(r[1]), "=r"(r[2]), "=r"(r[3]) : "r"(addr));
}
__device__ __forceinline__ void mma16816(float* c, const uint32_t* a, const uint32_t* b) {
    asm volatile("mma.sync.aligned.m16n8k16.row.col.f32.f16.f16.f32 "
        "{%0,%1,%2,%3}, {%4,%5,%6,%7}, {%8,%9}, {%0,%1,%2,%3};"
        : "+f"(c[0]), "+f"(c[1]), "+f"(c[2]), "+f"(c[3])
        : "r"(a[0]), "r"(a[1]), "r"(a[2]), "r"(a[3]), "r"(b[0]), "r"(b[1]));
}
__device__ __forceinline__ void mma16816h(uint32_t* c, const uint32_t* a, const uint32_t* b) {
    asm volatile("mma.sync.aligned.m16n8k16.row.col.f16.f16.f16.f16 "
        "{%0,%1}, {%2,%3,%4,%5}, {%6,%7}, {%0,%1};"
        : "+r"(c[0]), "+r"(c[1])
        : "r"(a[0]), "r"(a[1]), "r"(a[2]), "r"(a[3]), "r"(b[0]), "r"(b[1]));
}
__device__ __forceinline__ void cpasync16(uint32_t dst, const void* src) {
    asm volatile("cp.async.cg.shared.global [%0], [%1], 16;"
        :: "r"(dst), "l"(__cvta_generic_to_global(src)));
}
__device__ __forceinline__ void cp_commit() { asm volatile("cp.async.commit_group;" ::); }
__device__ __forceinline__ void cp_waitg(int n) {
    if (n == 0) asm volatile("cp.async.wait_group 0;" ::: "memory");
    else asm volatile("cp.async.wait_group 1;" ::: "memory");
}

// ---------------------------------------------------------------------------
// Kernel 1 (merged projections): grid.y selects work group
//   y 0..3 : Q  (16 e-outputs per group)   y 4..7 : K    y 8..9 : V
// ---------------------------------------------------------------------------
__global__ __launch_bounds__(128) void proj_kernel(
    const float* __restrict__ xt, const float* __restrict__ xo,
    const float* __restrict__ qw, const float* __restrict__ qb,
    const float* __restrict__ kw, const float* __restrict__ kb,
    const float* __restrict__ vw, const float* __restrict__ vb)
{
    __shared__ float ws[16*CT];
    __shared__ float bs[16];
    const int tid = threadIdx.x;
    const int grp = blockIdx.y;
    const int idx = blockIdx.x*128 + tid;
    const int b = idx / NQ;

    if (grp < 4) {
        int eb = grp * 16;
        for (int i = tid; i < 16*CT; i += 128) ws[i] = qw[eb*CT + i] * QSCALE;
        if (tid < 16) bs[tid] = qb[eb + tid] * QSCALE;
        __syncthreads();

        int n = idx % NQ;
        int y = n / WO, x = n % WO;
        float sy = (y + 0.5f) * (1.0f/3.0f) - 0.5f;
        float sx = (x + 0.5f) * (1.0f/3.0f) - 0.5f;
        float fy0 = floorf(sy), fx0 = floorf(sx);
        float fy = sy - fy0, fx = sx - fx0;
        int y0 = (int)fy0, x0 = (int)fx0;
        int y0c = max(y0, 0), y1c = min(y0+1, HI-1);
        int x0c = max(x0, 0), x1c = min(x0+1, WI-1);
        float w00 = (1.f-fy)*(1.f-fx), w01 = (1.f-fy)*fx;
        float w10 = fy*(1.f-fx),       w11 = fy*fx;

        float xv[CT];
        const float* tb = xt + b*CT*HI*WI;
        #pragma unroll
        for (int c = 0; c < CT; c++) {
            const float* p = tb + c*HI*WI;
            xv[c] = w00*p[y0c*WI+x0c] + w01*p[y0c*WI+x1c]
                  + w10*p[y1c*WI+x0c] + w11*p[y1c*WI+x1c];
        }
        float s[16];
        #pragma unroll
        for (int j = 0; j < 16; j++) {
            float acc = bs[j];
            const float4* w4 = (const float4*)(ws + j*CT);
            #pragma unroll
            for (int c4 = 0; c4 < CT/4; c4++) {
                float4 w = w4[c4];
                acc = fmaf(w.x, xv[4*c4+0], acc);
                acc = fmaf(w.y, xv[4*c4+1], acc);
                acc = fmaf(w.z, xv[4*c4+2], acc);
                acc = fmaf(w.w, xv[4*c4+3], acc);
            }
            s[j] = acc;
        }
        uint4* dst = (uint4*)(g_qh + (size_t)idx*ED + eb);
        #pragma unroll
        for (int h = 0; h < 2; h++) {
            uint4 u;
            u.x = pack2(s[8*h+0], s[8*h+1]); u.y = pack2(s[8*h+2], s[8*h+3]);
            u.z = pack2(s[8*h+4], s[8*h+5]); u.w = pack2(s[8*h+6], s[8*h+7]);
            dst[h] = u;
        }
    } else {
        bool isv = grp >= 8;
        int ob = (isv ? (grp-8) : (grp-4)) * 16;
        const float* W  = isv ? vw : kw;
        const float* Bv = isv ? vb : kb;
        for (int i = tid; i < 16*CO; i += 128) ws[i] = W[ob*CO + i];
        if (tid < 16) bs[tid] = Bv[ob + tid];
        __syncthreads();

        int m = idx % NQ;
        float xv[CO];
        const float* p = xo + (size_t)b*CO*NQ + m;
        #pragma unroll
        for (int c = 0; c < CO; c++) xv[c] = p[(size_t)c*NQ];

        float s[16];
        #pragma unroll
        for (int j = 0; j < 16; j++) {
            float acc = bs[j];
            const float4* w4 = (const float4*)(ws + j*CO);
            #pragma unroll
            for (int c4 = 0; c4 < CO/4; c4++) {
                float4 w = w4[c4];
                acc = fmaf(w.x, xv[4*c4+0], acc);
                acc = fmaf(w.y, xv[4*c4+1], acc);
                acc = fmaf(w.z, xv[4*c4+2], acc);
                acc = fmaf(w.w, xv[4*c4+3], acc);
            }
            s[j] = acc;
        }
        __half* dst = (isv ? g_vh + (size_t)idx*CO : g_kh + (size_t)idx*ED) + ob;
        uint4* d4 = (uint4*)dst;
        #pragma unroll
        for (int h = 0; h < 2; h++) {
            uint4 u;
            u.x = pack2(s[8*h+0], s[8*h+1]); u.y = pack2(s[8*h+2], s[8*h+3]);
            u.z = pack2(s[8*h+4], s[8*h+5]); u.w = pack2(s[8*h+6], s[8*h+7]);
            d4[h] = u;
        }
    }
}

// ---------------------------------------------------------------------------
// Kernel 2: 3-way split-K flash attention, M=32 per warp (4 warps/CTA),
// 3 CTAs/SM (smem 61440, regs capped by launch_bounds(128,3)).
// NBUF=3 ring: the t+2 prefetch is issued AFTER the top-of-tile barrier, so
// its target buffer (t-1)%3 is provably no longer being read.
// Last-arriving split CTA does the combine + conv + BN + ReLU.
// ---------------------------------------------------------------------------
__global__ __launch_bounds__(128, 3) void attn_kernel(
    const float* __restrict__ ow,
    const float* __restrict__ gam, const float* __restrict__ bet,
    const float* __restrict__ mu,  const float* __restrict__ var,
    float* __restrict__ out)
{
    extern __shared__ __align__(16) char sm[];
    float* osm = (float*)(sm + SM_OSM);

    const int tid = threadIdx.x;
    const int l = tid & 31, w = tid >> 5;   // 4 warps
    const int b = blockIdx.y;
    const int z = blockIdx.z;
    const int r = b*NQB + blockIdx.x;       // qblock id

    uint32_t smb  = (uint32_t)__cvta_generic_to_shared(sm);
    uint32_t qs_b = smb + SM_Q;
    uint32_t ks_b = smb + SM_K;
    uint32_t vs_b = smb + SM_V;

    // ---- stage Q tile to smem (rows of 72 halves = 144B) ----
    {
        const uint4* qsrc = (const uint4*)(g_qh + ((size_t)b*NQ + blockIdx.x*QB)*ED);
        #pragma unroll
        for (int i = 0; i < 8; i++) {
            int c = tid + i*128;
            int row = c >> 3, c8 = c & 7;
            *(uint4*)(sm + SM_Q + row*144 + c8*16) = qsrc[row*8 + c8];
        }
    }
    __syncthreads();

    // ---- Q fragments: 2 row-halves x 4 k-steps ----
    uint32_t qa[2][4][4];
    {
        int colh = l >> 4;
        #pragma unroll
        for (int h = 0; h < 2; h++) {
            int row = 32*w + 16*h + (l & 15);
            #pragma unroll
            for (int kk = 0; kk < 4; kk++)
                ldsm4(qa[h][kk], qs_b + row*144 + (16*kk + 8*colh)*2);
        }
    }

    const __half* kg = g_kh + (size_t)b*NQ*ED + (size_t)z*NT2*KT*ED;
    const __half* vg = g_vh + (size_t)b*NQ*CO + (size_t)z*NT2*KT*CO;

    auto load_tile = [&](int t, int buf) {
        #pragma unroll
        for (int i = 0; i < 4; i++) {
            int c = tid + i*128;
            int row = c >> 3, c8 = c & 7;
            cpasync16(ks_b + buf*9216 + row*144 + c8*16,
                      kg + (size_t)(t*KT + row)*ED + c8*8);
        }
        #pragma unroll
        for (int i = 0; i < 2; i++) {
            int c = tid + i*128;
            int row = c >> 2, c4 = c & 3;
            cpasync16(vs_b + buf*5120 + row*80 + c4*16,
                      vg + (size_t)(t*KT + row)*CO + c4*8);
        }
        cp_commit();
    };

    const uint32_t k_lane = (uint32_t)((8*(l >> 4) + (l & 7))*144 + ((l & 15) >> 3)*16);
    const int vqd = l >> 3;
    const uint32_t v_lane = (uint32_t)(((vqd & 1)*8 + (l & 7))*80 + (vqd >> 1)*16);

    float oacc[2][4][4];
    #pragma unroll
    for (int h = 0; h < 2; h++)
        #pragma unroll
        for (int ot = 0; ot < 4; ot++)
            #pragma unroll
            for (int rr = 0; rr < 4; rr++) oacc[h][ot][rr] = 0.f;
    float dacc[2][4] = {{0.f,0.f,0.f,0.f},{0.f,0.f,0.f,0.f}};
    const uint32_t bones[2] = { ONES2, ONES2 };

    load_tile(0, 0);
    load_tile(1, 1);

    int cbuf = 0, lbuf = 2;
    for (int t = 0; t < NT2; t++) {
        cp_waitg((t + 1 < NT2) ? 1 : 0);
        __syncthreads();   // buffer t visible; all warps done with tile t-1
        if (t + 2 < NT2) load_tile(t + 2, lbuf);   // safe post-barrier (NBUF=3)

        uint32_t kbase = ks_b + cbuf*9216 + k_lane;
        uint32_t vbase = vs_b + cbuf*5120 + v_lane;

        // sc[h][j][2] : S f16 accumulators; overwritten in place by exp2 -> P
        uint32_t sc[2][8][2];
        #pragma unroll
        for (int h = 0; h < 2; h++)
            #pragma unroll
            for (int j = 0; j < 8; j++) { sc[h][j][0] = 0u; sc[h][j][1] = 0u; }

        // ---- S, keys 0..31: each kb fragment feeds both row-halves ----
        #pragma unroll
        for (int kk = 0; kk < 4; kk++) {
            uint32_t kb[8];
            ldsm4(&kb[0], kbase + 0*2304 + kk*32);
            ldsm4(&kb[4], kbase + 1*2304 + kk*32);
            #pragma unroll
            for (int j = 0; j < 4; j++) {
                mma16816h(sc[0][j], qa[0][kk], &kb[2*j]);
                mma16816h(sc[1][j], qa[1][kk], &kb[2*j]);
            }
        }
        // ex2 keys 0..31
        #pragma unroll
        for (int h = 0; h < 2; h++)
            #pragma unroll
            for (int j = 0; j < 4; j++) {
                sc[h][j][0] = h2ex2(sc[h][j][0]);
                sc[h][j][1] = h2ex2(sc[h][j][1]);
            }
        // ---- S, keys 32..63 — fills tensor pipe during ex2 above ----
        #pragma unroll
        for (int kk = 0; kk < 4; kk++) {
            uint32_t kb[8];
            ldsm4(&kb[0], kbase + 2*2304 + kk*32);
            ldsm4(&kb[4], kbase + 3*2304 + kk*32);
            #pragma unroll
            for (int j = 0; j < 4; j++) {
                mma16816h(sc[0][4+j], qa[0][kk], &kb[2*j]);
                mma16816h(sc[1][4+j], qa[1][kk], &kb[2*j]);
            }
        }
        // ---- PV, keys 0..31 ----
        #pragma unroll
        for (int kk2 = 0; kk2 < 2; kk2++) {
            uint32_t vb[8];
            ldsm4t(&vb[0], vbase + kk2*1280);
            ldsm4t(&vb[4], vbase + kk2*1280 + 32);
            #pragma unroll
            for (int h = 0; h < 2; h++) {
                uint32_t paH[4] = { sc[h][2*kk2][0], sc[h][2*kk2][1],
                                    sc[h][2*kk2+1][0], sc[h][2*kk2+1][1] };
                #pragma unroll
                for (int ot = 0; ot < 4; ot++)
                    mma16816(oacc[h][ot], paH, &vb[2*ot]);
                mma16816(dacc[h], paH, bones);
            }
        }
        // ex2 keys 32..63
        #pragma unroll
        for (int h = 0; h < 2; h++)
            #pragma unroll
            for (int j = 4; j < 8; j++) {
                sc[h][j][0] = h2ex2(sc[h][j][0]);
                sc[h][j][1] = h2ex2(sc[h][j][1]);
            }
        // ---- PV, keys 32..63 ----
        #pragma unroll
        for (int kk2 = 2; kk2 < 4; kk2++) {
            uint32_t vb[8];
            ldsm4t(&vb[0], vbase + kk2*1280);
            ldsm4t(&vb[4], vbase + kk2*1280 + 32);
            #pragma unroll
            for (int h = 0; h < 2; h++) {
                uint32_t paH[4] = { sc[h][2*kk2][0], sc[h][2*kk2][1],
                                    sc[h][2*kk2+1][0], sc[h][2*kk2+1][1] };
                #pragma unroll
                for (int ot = 0; ot < 4; ot++)
                    mma16816(oacc[h][ot], paH, &vb[2*ot]);
                mma16816(dacc[h], paH, bones);
            }
        }

        cbuf = (cbuf == 2) ? 0 : cbuf + 1;
        lbuf = (lbuf == 2) ? 0 : lbuf + 1;
    }

    // ---- stage unnormalized partials (num[32] + den) into smem ----
    __syncthreads();
    {
        int g = l >> 2, tig = l & 3;
        #pragma unroll
        for (int h = 0; h < 2; h++) {
            int r0 = 32*w + 16*h + g, r1 = r0 + 8;
            #pragma unroll
            for (int ot = 0; ot < 4; ot++) {
                osm[r0*PSTRIDE + 8*ot + 2*tig    ] = oacc[h][ot][0];
                osm[r0*PSTRIDE + 8*ot + 2*tig + 1] = oacc[h][ot][1];
                osm[r1*PSTRIDE + 8*ot + 2*tig    ] = oacc[h][ot][2];
                osm[r1*PSTRIDE + 8*ot + 2*tig + 1] = oacc[h][ot][3];
            }
            if (tig == 0) {
                osm[r0*PSTRIDE + 32] = dacc[h][0];
                osm[r1*PSTRIDE + 32] = dacc[h][2];
            }
        }
    }
    __syncthreads();

    // ---- publish partial; last CTA of the split trio combines ----
    {
        float* dst = g_part + (size_t)z*ZSTRIDE + (size_t)r * (QB*PSTRIDE);
        #pragma unroll
        for (int i = 0; i < (QB*PSTRIDE)/128; i++)
            dst[tid + i*128] = osm[tid + i*128];
    }
    __threadfence();
    __syncthreads();

    __shared__ int s_flag;
    if (tid == 0) {
        int old = atomicAdd(&g_sync[r], 1);
        s_flag = old;
        if (old == NSPLIT-1) atomicExch(&g_sync[r], 0);   // reset for graph replay
    }
    __syncthreads();
    if (s_flag != NSPLIT-1) return;
    __threadfence();   // acquire other CTAs' partials

    // ---- consumer: combine all partials (fixed z order), conv+BN+ReLU ----
    float* wsm = (float*)(sm + SM_WSM);
    float* bna = (float*)(sm + SM_BNA);
    float* bnb = (float*)(sm + SM_BNB);
    for (int i = tid; i < CT*CO; i += 128) wsm[i] = ow[i];
    if (tid < CT) {
        float a = gam[tid] * rsqrtf(var[tid] + 1e-5f);
        bna[tid] = a;
        bnb[tid] = bet[tid] - mu[tid]*a;
    }
    __syncthreads();

    {
        int q = tid;
        const float* p0 = g_part + (size_t)r * (QB*PSTRIDE) + q*PSTRIDE;
        const float* p1 = p0 + ZSTRIDE;
        const float* p2 = p1 + ZSTRIDE;

        float den = __ldcg(p0 + 32) + __ldcg(p1 + 32) + __ldcg(p2 + 32);
        float inv = 1.0f / den;
        float a[CO];
        #pragma unroll
        for (int o4 = 0; o4 < CO/4; o4++) {
            float4 u = __ldcg((const float4*)p0 + o4);
            float4 v = __ldcg((const float4*)p1 + o4);
            float4 t = __ldcg((const float4*)p2 + o4);
            a[4*o4+0] = (u.x + v.x + t.x) * inv;
            a[4*o4+1] = (u.y + v.y + t.y) * inv;
            a[4*o4+2] = (u.z + v.z + t.z) * inv;
            a[4*o4+3] = (u.w + v.w + t.w) * inv;
        }

        float* op = out + (size_t)b*CT*NQ + blockIdx.x*QB + q;
        #pragma unroll 4
        for (int ct = 0; ct < CT; ct++) {
            float g = 0.f;
            const float4* w4 = (const float4*)(wsm + ct*CO);
            #pragma unroll
            for (int o4 = 0; o4 < CO/4; o4++) {
                float4 wv = w4[o4];
                g = fmaf(wv.x, a[4*o4+0], g);
                g = fmaf(wv.y, a[4*o4+1], g);
                g = fmaf(wv.z, a[4*o4+2], g);
                g = fmaf(wv.w, a[4*o4+3], g);
            }
            g = fmaf(g, bna[ct], bnb[ct]);
            op[(size_t)ct*NQ] = fmaxf(g, 0.f);
        }
    }
}

// ---------------------------------------------------------------------------
extern "C" void kernel_launch(void* const* d_in, const int* in_sizes, int n_in,
                              void* d_out, int out_size)
{
    const float* xt  = (const float*)d_in[0];
    const float* xo  = (const float*)d_in[1];
    const float* qw  = (const float*)d_in[2];
    const float* qb  = (const float*)d_in[3];
    const float* kw  = (const float*)d_in[4];
    const float* kb  = (const float*)d_in[5];
    const float* vw  = (const float*)d_in[6];
    const float* vb  = (const float*)d_in[7];
    const float* ow  = (const float*)d_in[8];
    const float* gam = (const float*)d_in[9];
    const float* bet = (const float*)d_in[10];
    const float* mu  = (const float*)d_in[11];
    const float* var = (const float*)d_in[12];
    float* out = (float*)d_out;

    static int smem_set = 0;
    if (!smem_set) {
        cudaFuncSetAttribute(attn_kernel,
            cudaFuncAttributeMaxDynamicSharedMemorySize, SM_TOTAL);
        smem_set = 1;
    }

    dim3 gp((BATCH*NQ)/128, 10);
    proj_kernel<<<gp, 128>>>(xt, xo, qw, qb, kw, kb, vw, vb);
    dim3 ga(NQB, BATCH, NSPLIT);
    attn_kernel<<<ga, 128, SM_TOTAL>>>(ow, gam, bet, mu, var, out);
}

// round 11
// speedup vs baseline: 1.4729x; 1.4729x over previous
#include <cuda_runtime.h>
#include <cuda_fp16.h>
#include <cstdint>
#include <math.h>

#define BATCH 2
#define CT 64      // thermal channels (= output channels)
#define CO 32      // optical channels (= V dim)
#define ED 64      // embed dim E
#define HI 32
#define WI 32
#define HO 96
#define WO 96
#define NQ (HO*WO)     // 9216
#define QB 128         // queries per CTA
#define KT 64          // keys per smem tile
#define NSPLIT 2       // key-dimension split
#define NT2 (NQ/KT/NSPLIT)   // 72 tiles per CTA
#define NQB (NQ/QB)    // 72 query blocks
#define QSCALE 0.180336880f   // (1/sqrt(64)) * log2(e): softmax becomes exp2(s)
#define PSTRIDE 36     // padded row: 32 num + den@32 + pad (144B, 16B aligned)
#define NBUF 4         // K/V smem ring depth

// dynamic smem layout (75776 B total) -> 2 CTAs/SM
#define SM_Q   0                      // [128][144B]
#define SM_K   18432                  // 4 x [64 rows][144B]
#define SM_V   55296                  // 4 x [64 rows][80B]
#define SM_TOTAL 75776
// epilogue overlays
#define SM_OSM 0                      // [128][36] f32
#define SM_WSM 18432                  // [64][32] f32
#define SM_BNA 26624
#define SM_BNB 26880

// scratch (allocation-free: __device__ globals)
__device__ __half g_qh[BATCH*NQ*ED];   // [b][n][e], pre-scaled by QSCALE
__device__ __half g_kh[BATCH*NQ*ED];   // [b][m][e]
__device__ __half g_vh[BATCH*NQ*CO];   // [b][m][o]
__device__ float  g_part[NSPLIT*BATCH*NQB*QB*PSTRIDE];  // split-K partials
__device__ int    g_sync[BATCH*NQB];   // per-qblock arrival counters

// ---------------------------------------------------------------------------
// helpers
// ---------------------------------------------------------------------------
__device__ __forceinline__ uint32_t pack2(float a, float b) {
    __half2 h = __floats2half2_rn(a, b);
    return *(uint32_t*)&h;
}
__device__ __forceinline__ uint32_t h2ex2(uint32_t x) {
    uint32_t y; asm("ex2.approx.f16x2 %0, %1;" : "=r"(y) : "r"(x)); return y;
}
__device__ __forceinline__ void ldsm4(uint32_t* r, uint32_t addr) {
    asm volatile("ldmatrix.sync.aligned.m8n8.x4.shared.b16 {%0,%1,%2,%3}, [%4];"
        : "=r"(r[0]), "=r"(r[1]), "=r"(r[2]), "=r"(r[3]) : "r"(addr));
}
__device__ __forceinline__ void ldsm4t(uint32_t* r, uint32_t addr) {
    asm volatile("ldmatrix.sync.aligned.m8n8.x4.trans.shared.b16 {%0,%1,%2,%3}, [%4];"
        : "=r"(r[0]), "=r"(r[1]), "=r"(r[2]), "=r"(r[3]) : "r"(addr));
}
__device__ __forceinline__ void mma16816(float* c, const uint32_t* a, const uint32_t* b) {
    asm volatile("mma.sync.aligned.m16n8k16.row.col.f32.f16.f16.f32 "
        "{%0,%1,%2,%3}, {%4,%5,%6,%7}, {%8,%9}, {%0,%1,%2,%3};"
        : "+f"(c[0]), "+f"(c[1]), "+f"(c[2]), "+f"(c[3])
        : "r"(a[0]), "r"(a[1]), "r"(a[2]), "r"(a[3]), "r"(b[0]), "r"(b[1]));
}
__device__ __forceinline__ void mma16816h(uint32_t* c, const uint32_t* a, const uint32_t* b) {
    asm volatile("mma.sync.aligned.m16n8k16.row.col.f16.f16.f16.f16 "
        "{%0,%1}, {%2,%3,%4,%5}, {%6,%7}, {%0,%1};"
        : "+r"(c[0]), "+r"(c[1])
        : "r"(a[0]), "r"(a[1]), "r"(a[2]), "r"(a[3]), "r"(b[0]), "r"(b[1]));
}
__device__ __forceinline__ void cpasync16(uint32_t dst, const void* src) {
    asm volatile("cp.async.cg.shared.global [%0], [%1], 16;"
        :: "r"(dst), "l"(__cvta_generic_to_global(src)));
}
__device__ __forceinline__ void cp_commit() { asm volatile("cp.async.commit_group;" ::); }
__device__ __forceinline__ void cp_waitg(int n) {
    if (n == 0) asm volatile("cp.async.wait_group 0;" ::: "memory");
    else if (n == 1) asm volatile("cp.async.wait_group 1;" ::: "memory");
    else asm volatile("cp.async.wait_group 2;" ::: "memory");
}

// ---------------------------------------------------------------------------
// Kernel 1 (merged projections): grid.y selects work group
//   y 0..3 : Q  (16 e-outputs per group)   y 4..7 : K    y 8..9 : V
// ---------------------------------------------------------------------------
__global__ __launch_bounds__(128) void proj_kernel(
    const float* __restrict__ xt, const float* __restrict__ xo,
    const float* __restrict__ qw, const float* __restrict__ qb,
    const float* __restrict__ kw, const float* __restrict__ kb,
    const float* __restrict__ vw, const float* __restrict__ vb)
{
    __shared__ float ws[16*CT];
    __shared__ float bs[16];
    const int tid = threadIdx.x;
    const int grp = blockIdx.y;
    const int idx = blockIdx.x*128 + tid;
    const int b = idx / NQ;

    if (grp < 4) {
        int eb = grp * 16;
        for (int i = tid; i < 16*CT; i += 128) ws[i] = qw[eb*CT + i] * QSCALE;
        if (tid < 16) bs[tid] = qb[eb + tid] * QSCALE;
        __syncthreads();

        int n = idx % NQ;
        int y = n / WO, x = n % WO;
        float sy = (y + 0.5f) * (1.0f/3.0f) - 0.5f;
        float sx = (x + 0.5f) * (1.0f/3.0f) - 0.5f;
        float fy0 = floorf(sy), fx0 = floorf(sx);
        float fy = sy - fy0, fx = sx - fx0;
        int y0 = (int)fy0, x0 = (int)fx0;
        int y0c = max(y0, 0), y1c = min(y0+1, HI-1);
        int x0c = max(x0, 0), x1c = min(x0+1, WI-1);
        float w00 = (1.f-fy)*(1.f-fx), w01 = (1.f-fy)*fx;
        float w10 = fy*(1.f-fx),       w11 = fy*fx;

        float xv[CT];
        const float* tb = xt + b*CT*HI*WI;
        #pragma unroll
        for (int c = 0; c < CT; c++) {
            const float* p = tb + c*HI*WI;
            xv[c] = w00*p[y0c*WI+x0c] + w01*p[y0c*WI+x1c]
                  + w10*p[y1c*WI+x0c] + w11*p[y1c*WI+x1c];
        }
        float s[16];
        #pragma unroll
        for (int j = 0; j < 16; j++) {
            float acc = bs[j];
            const float4* w4 = (const float4*)(ws + j*CT);
            #pragma unroll
            for (int c4 = 0; c4 < CT/4; c4++) {
                float4 w = w4[c4];
                acc = fmaf(w.x, xv[4*c4+0], acc);
                acc = fmaf(w.y, xv[4*c4+1], acc);
                acc = fmaf(w.z, xv[4*c4+2], acc);
                acc = fmaf(w.w, xv[4*c4+3], acc);
            }
            s[j] = acc;
        }
        uint4* dst = (uint4*)(g_qh + (size_t)idx*ED + eb);
        #pragma unroll
        for (int h = 0; h < 2; h++) {
            uint4 u;
            u.x = pack2(s[8*h+0], s[8*h+1]); u.y = pack2(s[8*h+2], s[8*h+3]);
            u.z = pack2(s[8*h+4], s[8*h+5]); u.w = pack2(s[8*h+6], s[8*h+7]);
            dst[h] = u;
        }
    } else {
        bool isv = grp >= 8;
        int ob = (isv ? (grp-8) : (grp-4)) * 16;
        const float* W  = isv ? vw : kw;
        const float* Bv = isv ? vb : kb;
        for (int i = tid; i < 16*CO; i += 128) ws[i] = W[ob*CO + i];
        if (tid < 16) bs[tid] = Bv[ob + tid];
        __syncthreads();

        int m = idx % NQ;
        float xv[CO];
        const float* p = xo + (size_t)b*CO*NQ + m;
        #pragma unroll
        for (int c = 0; c < CO; c++) xv[c] = p[(size_t)c*NQ];

        float s[16];
        #pragma unroll
        for (int j = 0; j < 16; j++) {
            float acc = bs[j];
            const float4* w4 = (const float4*)(ws + j*CO);
            #pragma unroll
            for (int c4 = 0; c4 < CO/4; c4++) {
                float4 w = w4[c4];
                acc = fmaf(w.x, xv[4*c4+0], acc);
                acc = fmaf(w.y, xv[4*c4+1], acc);
                acc = fmaf(w.z, xv[4*c4+2], acc);
                acc = fmaf(w.w, xv[4*c4+3], acc);
            }
            s[j] = acc;
        }
        __half* dst = (isv ? g_vh + (size_t)idx*CO : g_kh + (size_t)idx*ED) + ob;
        uint4* d4 = (uint4*)dst;
        #pragma unroll
        for (int h = 0; h < 2; h++) {
            uint4 u;
            u.x = pack2(s[8*h+0], s[8*h+1]); u.y = pack2(s[8*h+2], s[8*h+3]);
            u.z = pack2(s[8*h+4], s[8*h+5]); u.w = pack2(s[8*h+6], s[8*h+7]);
            d4[h] = u;
        }
    }
}

// ---------------------------------------------------------------------------
// Kernel 2: split-K flash attention, M=32 per warp (4 warps, 128 threads),
// 2 CTAs/SM. Hoisted ldsm bursts (K frags for a 32-key half loaded before the
// MMA burst; same for V). den on fma/alu pipes via EXACT fp32 adds of
// individually-converted f16 P values (no serial tensor-pipe den chain).
// Fused split-combine epilogue. 4-deep ring, one barrier per tile.
// ---------------------------------------------------------------------------
__global__ __launch_bounds__(128, 2) void attn_kernel(
    const float* __restrict__ ow,
    const float* __restrict__ gam, const float* __restrict__ bet,
    const float* __restrict__ mu,  const float* __restrict__ var,
    float* __restrict__ out)
{
    extern __shared__ __align__(16) char sm[];
    float* osm = (float*)(sm + SM_OSM);

    const int tid = threadIdx.x;
    const int l = tid & 31, w = tid >> 5;   // 4 warps
    const int b = blockIdx.y;
    const int z = blockIdx.z;
    const int r = b*NQB + blockIdx.x;       // qblock id

    uint32_t smb  = (uint32_t)__cvta_generic_to_shared(sm);
    uint32_t qs_b = smb + SM_Q;
    uint32_t ks_b = smb + SM_K;
    uint32_t vs_b = smb + SM_V;

    // ---- stage Q tile to smem (rows of 72 halves = 144B) ----
    {
        const uint4* qsrc = (const uint4*)(g_qh + ((size_t)b*NQ + blockIdx.x*QB)*ED);
        #pragma unroll
        for (int i = 0; i < 8; i++) {
            int c = tid + i*128;
            int row = c >> 3, c8 = c & 7;
            *(uint4*)(sm + SM_Q + row*144 + c8*16) = qsrc[row*8 + c8];
        }
    }
    __syncthreads();

    // ---- Q fragments: 2 row-halves x 4 k-steps (warp w owns rows [32w,32w+32)) ----
    uint32_t qa[2][4][4];
    {
        int colh = l >> 4;
        #pragma unroll
        for (int h = 0; h < 2; h++) {
            int row = 32*w + 16*h + (l & 15);
            #pragma unroll
            for (int kk = 0; kk < 4; kk++)
                ldsm4(qa[h][kk], qs_b + row*144 + (16*kk + 8*colh)*2);
        }
    }

    const __half* kg = g_kh + (size_t)b*NQ*ED + (size_t)z*NT2*KT*ED;
    const __half* vg = g_vh + (size_t)b*NQ*CO + (size_t)z*NT2*KT*CO;

    auto load_tile = [&](int t) {
        int buf = t & (NBUF-1);
        #pragma unroll
        for (int i = 0; i < 4; i++) {
            int c = tid + i*128;
            int row = c >> 3, c8 = c & 7;
            cpasync16(ks_b + buf*9216 + row*144 + c8*16,
                      kg + (size_t)(t*KT + row)*ED + c8*8);
        }
        #pragma unroll
        for (int i = 0; i < 2; i++) {
            int c = tid + i*128;
            int row = c >> 2, c4 = c & 3;
            cpasync16(vs_b + buf*5120 + row*80 + c4*16,
                      vg + (size_t)(t*KT + row)*CO + c4*8);
        }
        cp_commit();
    };

    const uint32_t k_lane = (uint32_t)((8*(l >> 4) + (l & 7))*144 + ((l & 15) >> 3)*16);
    const int vqd = l >> 3;
    const uint32_t v_lane = (uint32_t)(((vqd & 1)*8 + (l & 7))*80 + (vqd >> 1)*16);

    float oacc[2][4][4];
    #pragma unroll
    for (int h = 0; h < 2; h++)
        #pragma unroll
        for (int ot = 0; ot < 4; ot++)
            #pragma unroll
            for (int rr = 0; rr < 4; rr++) oacc[h][ot][rr] = 0.f;
    float den[2][2] = {{0.f,0.f},{0.f,0.f}};   // [row-half h][reg-half]

    load_tile(0);
    load_tile(1);

    for (int t = 0; t < NT2; t++) {
        if (t + 2 < NT2) { load_tile(t + 2); cp_waitg(2); }
        else if (t + 1 < NT2) cp_waitg(1);
        else cp_waitg(0);
        __syncthreads();

        int buf = t & (NBUF-1);
        uint32_t kbase = ks_b + buf*9216 + k_lane;
        uint32_t vbase = vs_b + buf*5120 + v_lane;

        // sc[h][j][2] : S f16 accumulators; overwritten in place by exp2 -> P
        uint32_t sc[2][8][2];
        #pragma unroll
        for (int h = 0; h < 2; h++)
            #pragma unroll
            for (int j = 0; j < 8; j++) { sc[h][j][0] = 0u; sc[h][j][1] = 0u; }

        // ---- S, keys 0..31: hoist all 8 K ldsm before the MMA burst ----
        {
            uint32_t kf[4][8];
            #pragma unroll
            for (int kk = 0; kk < 4; kk++) {
                ldsm4(&kf[kk][0], kbase + 0*2304 + kk*32);
                ldsm4(&kf[kk][4], kbase + 1*2304 + kk*32);
            }
            #pragma unroll
            for (int kk = 0; kk < 4; kk++)
                #pragma unroll
                for (int j = 0; j < 4; j++) {
                    mma16816h(sc[0][j], qa[0][kk], &kf[kk][2*j]);
                    mma16816h(sc[1][j], qa[1][kk], &kf[kk][2*j]);
                }
        }
        // ex2 keys 0..31 + exact fp32 den accumulation (fma/alu pipes)
        #pragma unroll
        for (int h = 0; h < 2; h++)
            #pragma unroll
            for (int j = 0; j < 4; j++) {
                sc[h][j][0] = h2ex2(sc[h][j][0]);
                sc[h][j][1] = h2ex2(sc[h][j][1]);
                float2 f0 = __half22float2(*(__half2*)&sc[h][j][0]);
                float2 f1 = __half22float2(*(__half2*)&sc[h][j][1]);
                den[h][0] += f0.x + f0.y;
                den[h][1] += f1.x + f1.y;
            }
        // ---- S, keys 32..63 (tensor pipe fed during ex2 above) ----
        {
            uint32_t kf[4][8];
            #pragma unroll
            for (int kk = 0; kk < 4; kk++) {
                ldsm4(&kf[kk][0], kbase + 2*2304 + kk*32);
                ldsm4(&kf[kk][4], kbase + 3*2304 + kk*32);
            }
            #pragma unroll
            for (int kk = 0; kk < 4; kk++)
                #pragma unroll
                for (int j = 0; j < 4; j++) {
                    mma16816h(sc[0][4+j], qa[0][kk], &kf[kk][2*j]);
                    mma16816h(sc[1][4+j], qa[1][kk], &kf[kk][2*j]);
                }
        }
        // ---- PV, keys 0..31: hoist both V ldsm pairs ----
        {
            uint32_t vf[2][8];
            #pragma unroll
            for (int kk2 = 0; kk2 < 2; kk2++) {
                ldsm4t(&vf[kk2][0], vbase + kk2*1280);
                ldsm4t(&vf[kk2][4], vbase + kk2*1280 + 32);
            }
            #pragma unroll
            for (int kk2 = 0; kk2 < 2; kk2++)
                #pragma unroll
                for (int h = 0; h < 2; h++) {
                    uint32_t paH[4] = { sc[h][2*kk2][0], sc[h][2*kk2][1],
                                        sc[h][2*kk2+1][0], sc[h][2*kk2+1][1] };
                    #pragma unroll
                    for (int ot = 0; ot < 4; ot++)
                        mma16816(oacc[h][ot], paH, &vf[kk2][2*ot]);
                }
        }
        // ex2 keys 32..63 + den
        #pragma unroll
        for (int h = 0; h < 2; h++)
            #pragma unroll
            for (int j = 4; j < 8; j++) {
                sc[h][j][0] = h2ex2(sc[h][j][0]);
                sc[h][j][1] = h2ex2(sc[h][j][1]);
                float2 f0 = __half22float2(*(__half2*)&sc[h][j][0]);
                float2 f1 = __half22float2(*(__half2*)&sc[h][j][1]);
                den[h][0] += f0.x + f0.y;
                den[h][1] += f1.x + f1.y;
            }
        // ---- PV, keys 32..63 ----
        {
            uint32_t vf[2][8];
            #pragma unroll
            for (int kk2 = 0; kk2 < 2; kk2++) {
                ldsm4t(&vf[kk2][0], vbase + (2+kk2)*1280);
                ldsm4t(&vf[kk2][4], vbase + (2+kk2)*1280 + 32);
            }
            #pragma unroll
            for (int kk2 = 0; kk2 < 2; kk2++)
                #pragma unroll
                for (int h = 0; h < 2; h++) {
                    uint32_t paH[4] = { sc[h][2*(2+kk2)][0], sc[h][2*(2+kk2)][1],
                                        sc[h][2*(2+kk2)+1][0], sc[h][2*(2+kk2)+1][1] };
                    #pragma unroll
                    for (int ot = 0; ot < 4; ot++)
                        mma16816(oacc[h][ot], paH, &vf[kk2][2*ot]);
                }
        }
    }

    // quad-reduce den (each lane held 16 of 64 key-columns per row)
    #pragma unroll
    for (int h = 0; h < 2; h++)
        #pragma unroll
        for (int rr = 0; rr < 2; rr++) {
            den[h][rr] += __shfl_xor_sync(0xffffffffu, den[h][rr], 1);
            den[h][rr] += __shfl_xor_sync(0xffffffffu, den[h][rr], 2);
        }

    // ---- stage unnormalized partials (num[32] + den) into smem ----
    __syncthreads();
    {
        int g = l >> 2, tig = l & 3;
        #pragma unroll
        for (int h = 0; h < 2; h++) {
            int r0 = 32*w + 16*h + g, r1 = r0 + 8;
            #pragma unroll
            for (int ot = 0; ot < 4; ot++) {
                osm[r0*PSTRIDE + 8*ot + 2*tig    ] = oacc[h][ot][0];
                osm[r0*PSTRIDE + 8*ot + 2*tig + 1] = oacc[h][ot][1];
                osm[r1*PSTRIDE + 8*ot + 2*tig    ] = oacc[h][ot][2];
                osm[r1*PSTRIDE + 8*ot + 2*tig + 1] = oacc[h][ot][3];
            }
            if (tig == 0) {
                osm[r0*PSTRIDE + 32] = den[h][0];
                osm[r1*PSTRIDE + 32] = den[h][1];
            }
        }
    }
    __syncthreads();

    // ---- publish partial; second CTA of the split pair combines ----
    {
        float* dst = g_part + (size_t)(z*BATCH*NQB + r) * (QB*PSTRIDE);
        #pragma unroll
        for (int i = 0; i < (QB*PSTRIDE)/128; i++)
            dst[tid + i*128] = osm[tid + i*128];
    }
    __threadfence();
    __syncthreads();

    __shared__ int s_flag;
    if (tid == 0) {
        int old = atomicAdd(&g_sync[r], 1);
        s_flag = old;
        if (old == 1) atomicExch(&g_sync[r], 0);   // reset for graph replay
    }
    __syncthreads();
    if (s_flag == 0) return;
    __threadfence();

    // ---- consumer: combine both partials, conv+BN+ReLU ----
    float* wsm = (float*)(sm + SM_WSM);
    float* bna = (float*)(sm + SM_BNA);
    float* bnb = (float*)(sm + SM_BNB);
    for (int i = tid; i < CT*CO; i += 128) wsm[i] = ow[i];
    if (tid < CT) {
        float a = gam[tid] * rsqrtf(var[tid] + 1e-5f);
        bna[tid] = a;
        bnb[tid] = bet[tid] - mu[tid]*a;
    }
    __syncthreads();

    {
        int q = tid;
        const float* p0 = g_part + (size_t)r * (QB*PSTRIDE) + q*PSTRIDE;
        const float* p1 = p0 + (size_t)BATCH*NQB*QB*PSTRIDE;

        float dsum = __ldcg(p0 + 32) + __ldcg(p1 + 32);
        float inv = 1.0f / dsum;
        float a[CO];
        #pragma unroll
        for (int o4 = 0; o4 < CO/4; o4++) {
            float4 u = __ldcg((const float4*)p0 + o4);
            float4 v = __ldcg((const float4*)p1 + o4);
            a[4*o4+0] = (u.x + v.x) * inv;
            a[4*o4+1] = (u.y + v.y) * inv;
            a[4*o4+2] = (u.z + v.z) * inv;
            a[4*o4+3] = (u.w + v.w) * inv;
        }

        float* op = out + (size_t)b*CT*NQ + blockIdx.x*QB + q;
        #pragma unroll 4
        for (int ct = 0; ct < CT; ct++) {
            float g = 0.f;
            const float4* w4 = (const float4*)(wsm + ct*CO);
            #pragma unroll
            for (int o4 = 0; o4 < CO/4; o4++) {
                float4 wv = w4[o4];
                g = fmaf(wv.x, a[4*o4+0], g);
                g = fmaf(wv.y, a[4*o4+1], g);
                g = fmaf(wv.z, a[4*o4+2], g);
                g = fmaf(wv.w, a[4*o4+3], g);
            }
            g = fmaf(g, bna[ct], bnb[ct]);
            op[(size_t)ct*NQ] = fmaxf(g, 0.f);
        }
    }
}

// ---------------------------------------------------------------------------
extern "C" void kernel_launch(void* const* d_in, const int* in_sizes, int n_in,
                              void* d_out, int out_size)
{
    const float* xt  = (const float*)d_in[0];
    const float* xo  = (const float*)d_in[1];
    const float* qw  = (const float*)d_in[2];
    const float* qb  = (const float*)d_in[3];
    const float* kw  = (const float*)d_in[4];
    const float* kb  = (const float*)d_in[5];
    const float* vw  = (const float*)d_in[6];
    const float* vb  = (const float*)d_in[7];
    const float* ow  = (const float*)d_in[8];
    const float* gam = (const float*)d_in[9];
    const float* bet = (const float*)d_in[10];
    const float* mu  = (const float*)d_in[11];
    const float* var = (const float*)d_in[12];
    float* out = (float*)d_out;

    static int smem_set = 0;
    if (!smem_set) {
        cudaFuncSetAttribute(attn_kernel,
            cudaFuncAttributeMaxDynamicSharedMemorySize, SM_TOTAL);
        smem_set = 1;
    }

    dim3 gp((BATCH*NQ)/128, 10);
    proj_kernel<<<gp, 128>>>(xt, xo, qw, qb, kw, kb, vw, vb);
    dim3 ga(NQB, BATCH, NSPLIT);
    attn_kernel<<<ga, 128, SM_TOTAL>>>(ow, gam, bet, mu, var, out);
}

// round 12
// speedup vs baseline: 1.5691x; 1.0653x over previous
#include <cuda_runtime.h>
#include <cuda_fp16.h>
#include <cstdint>
#include <math.h>

#define BATCH 2
#define CT 64      // thermal channels (= output channels)
#define CO 32      // optical channels (= V dim)
#define ED 64      // embed dim E
#define HI 32
#define WI 32
#define HO 96
#define WO 96
#define NQ (HO*WO)     // 9216
#define NS (HI*WI)     // 1024 (small-grid pixels)
#define QB 128         // queries per CTA
#define KT 64          // keys per smem tile
#define NSPLIT 2       // key-dimension split
#define NT2 (NQ/KT/NSPLIT)   // 72 tiles per CTA
#define NQB (NQ/QB)    // 72 query blocks
#define QSCALE 0.180336880f   // (1/sqrt(64)) * log2(e): softmax becomes exp2(s)
#define ONES2 0x3C003C00u     // f16x2 {1.0, 1.0}
#define PSTRIDE 36     // padded row: 32 num + den@32 + pad (144B, 16B aligned)
#define NBUF 4         // K/V smem ring depth

// dynamic smem layout (75776 B total) -> 2 CTAs/SM
#define SM_Q   0                      // [128][144B]
#define SM_K   18432                  // 4 x [64 rows][144B]
#define SM_V   55296                  // 4 x [64 rows][80B]
#define SM_TOTAL 75776
// epilogue overlays
#define SM_OSM 0                      // [128][36] f32
#define SM_WSM 18432                  // [64][32] f32
#define SM_BNA 26624
#define SM_BNB 26880

// scratch (allocation-free: __device__ globals)
__device__ float  g_qs[BATCH*NS*ED];   // small-grid Q (fp32, scaled+biased)
__device__ __half g_qh[BATCH*NQ*ED];   // [b][n][e], pre-scaled by QSCALE
__device__ __half g_kh[BATCH*NQ*ED];   // [b][m][e]
__device__ __half g_vh[BATCH*NQ*CO];   // [b][m][o]
__device__ float  g_part[NSPLIT*BATCH*NQB*QB*PSTRIDE];  // split-K partials
__device__ int    g_sync[BATCH*NQB];   // per-qblock arrival counters

// ---------------------------------------------------------------------------
// helpers
// ---------------------------------------------------------------------------
__device__ __forceinline__ uint32_t pack2(float a, float b) {
    __half2 h = __floats2half2_rn(a, b);
    return *(uint32_t*)&h;
}
__device__ __forceinline__ uint32_t h2ex2(uint32_t x) {
    uint32_t y; asm("ex2.approx.f16x2 %0, %1;" : "=r"(y) : "r"(x)); return y;
}
__device__ __forceinline__ void ldsm4(uint32_t* r, uint32_t addr) {
    asm volatile("ldmatrix.sync.aligned.m8n8.x4.shared.b16 {%0,%1,%2,%3}, [%4];"
        : "=r"(r[0]), "=r"(r[1]), "=r"(r[2]), "=r"(r[3]) : "r"(addr));
}
__device__ __forceinline__ void ldsm4t(uint32_t* r, uint32_t addr) {
    asm volatile("ldmatrix.sync.aligned.m8n8.x4.trans.shared.b16 {%0,%1,%2,%3}, [%4];"
        : "=r"(r[0]), "=r"(r[1]), "=r"(r[2]), "=r"(r[3]) : "r"(addr));
}
__device__ __forceinline__ void mma16816(float* c, const uint32_t* a, const uint32_t* b) {
    asm volatile("mma.sync.aligned.m16n8k16.row.col.f32.f16.f16.f32 "
        "{%0,%1,%2,%3}, {%4,%5,%6,%7}, {%8,%9}, {%0,%1,%2,%3};"
        : "+f"(c[0]), "+f"(c[1]), "+f"(c[2]), "+f"(c[3])
        : "r"(a[0]), "r"(a[1]), "r"(a[2]), "r"(a[3]), "r"(b[0]), "r"(b[1]));
}
__device__ __forceinline__ void mma16816h(uint32_t* c, const uint32_t* a, const uint32_t* b) {
    asm volatile("mma.sync.aligned.m16n8k16.row.col.f16.f16.f16.f16 "
        "{%0,%1}, {%2,%3,%4,%5}, {%6,%7}, {%0,%1};"
        : "+r"(c[0]), "+r"(c[1])
        : "r"(a[0]), "r"(a[1]), "r"(a[2]), "r"(a[3]), "r"(b[0]), "r"(b[1]));
}
__device__ __forceinline__ void cpasync16(uint32_t dst, const void* src) {
    asm volatile("cp.async.cg.shared.global [%0], [%1], 16;"
        :: "r"(dst), "l"(__cvta_generic_to_global(src)));
}
__device__ __forceinline__ void cp_commit() { asm volatile("cp.async.commit_group;" ::); }
__device__ __forceinline__ void cp_waitg(int n) {
    if (n == 0) asm volatile("cp.async.wait_group 0;" ::: "memory");
    else if (n == 1) asm volatile("cp.async.wait_group 1;" ::: "memory");
    else asm volatile("cp.async.wait_group 2;" ::: "memory");
}

// ---------------------------------------------------------------------------
// Kernel 0: Q projection at the SMALL grid (32x32) — conv commutes with
// bilinear upsample. Bias + QSCALE folded. grid (16, 4), 128 thr.
// ---------------------------------------------------------------------------
__global__ __launch_bounds__(128) void proj_qsmall_kernel(
    const float* __restrict__ xt, const float* __restrict__ qw,
    const float* __restrict__ qb)
{
    __shared__ float ws[16*CT];
    __shared__ float bs[16];
    const int tid = threadIdx.x;
    const int eb = blockIdx.y * 16;
    for (int i = tid; i < 16*CT; i += 128) ws[i] = qw[eb*CT + i] * QSCALE;
    if (tid < 16) bs[tid] = qb[eb + tid] * QSCALE;
    __syncthreads();

    const int idx = blockIdx.x*128 + tid;    // B*NS threads
    const int b = idx / NS, n = idx % NS;

    float xv[CT];
    const float* p = xt + (size_t)b*CT*NS + n;
    #pragma unroll
    for (int c = 0; c < CT; c++) xv[c] = p[(size_t)c*NS];

    float* dst = g_qs + (size_t)idx*ED + eb;
    #pragma unroll
    for (int j = 0; j < 16; j++) {
        float acc = bs[j];
        const float4* w4 = (const float4*)(ws + j*CT);
        #pragma unroll
        for (int c4 = 0; c4 < CT/4; c4++) {
            float4 w = w4[c4];
            acc = fmaf(w.x, xv[4*c4+0], acc);
            acc = fmaf(w.y, xv[4*c4+1], acc);
            acc = fmaf(w.z, xv[4*c4+2], acc);
            acc = fmaf(w.w, xv[4*c4+3], acc);
        }
        dst[j] = acc;
    }
}

// ---------------------------------------------------------------------------
// Kernel 1 (merged): grid.y selects work group
//   y 0    : Q upsample (bilinear on the PROJECTED small grid -> fp16)
//   y 1..4 : K  (16 e-outputs per group)
//   y 5..6 : V  (16 o-outputs per group)
// ---------------------------------------------------------------------------
__global__ __launch_bounds__(128) void proj_kernel(
    const float* __restrict__ xo,
    const float* __restrict__ kw, const float* __restrict__ kb,
    const float* __restrict__ vw, const float* __restrict__ vb)
{
    const int tid = threadIdx.x;
    const int grp = blockIdx.y;
    const int idx = blockIdx.x*128 + tid;     // B*NQ threads
    const int b = idx / NQ;

    if (grp == 0) {
        // ---- bilinear upsample of projected Q (half-pixel, edge clamp) ----
        int n = idx % NQ;
        int y = n / WO, x = n % WO;
        float sy = (y + 0.5f) * (1.0f/3.0f) - 0.5f;
        float sx = (x + 0.5f) * (1.0f/3.0f) - 0.5f;
        float fy0 = floorf(sy), fx0 = floorf(sx);
        float fy = sy - fy0, fx = sx - fx0;
        int y0 = (int)fy0, x0 = (int)fx0;
        int y0c = max(y0, 0), y1c = min(y0+1, HI-1);
        int x0c = max(x0, 0), x1c = min(x0+1, WI-1);
        float w00 = (1.f-fy)*(1.f-fx), w01 = (1.f-fy)*fx;
        float w10 = fy*(1.f-fx),       w11 = fy*fx;

        const float4* t00 = (const float4*)(g_qs + ((size_t)b*NS + y0c*WI + x0c)*ED);
        const float4* t01 = (const float4*)(g_qs + ((size_t)b*NS + y0c*WI + x1c)*ED);
        const float4* t10 = (const float4*)(g_qs + ((size_t)b*NS + y1c*WI + x0c)*ED);
        const float4* t11 = (const float4*)(g_qs + ((size_t)b*NS + y1c*WI + x1c)*ED);

        uint4* dst = (uint4*)(g_qh + (size_t)idx*ED);
        #pragma unroll
        for (int half = 0; half < 2; half++) {
            float s[32];
            #pragma unroll
            for (int i = 0; i < 8; i++) {
                int ii = half*8 + i;
                float4 a = t00[ii], c = t01[ii], d = t10[ii], e = t11[ii];
                s[4*i+0] = w00*a.x + w01*c.x + w10*d.x + w11*e.x;
                s[4*i+1] = w00*a.y + w01*c.y + w10*d.y + w11*e.y;
                s[4*i+2] = w00*a.z + w01*c.z + w10*d.z + w11*e.z;
                s[4*i+3] = w00*a.w + w01*c.w + w10*d.w + w11*e.w;
            }
            #pragma unroll
            for (int h = 0; h < 2; h++) {
                uint4 u;
                u.x = pack2(s[16*h+0],  s[16*h+1]);  u.y = pack2(s[16*h+2],  s[16*h+3]);
                u.z = pack2(s[16*h+4],  s[16*h+5]);  u.w = pack2(s[16*h+6],  s[16*h+7]);
                // second quad
                uint4 u2;
                u2.x = pack2(s[16*h+8],  s[16*h+9]);  u2.y = pack2(s[16*h+10], s[16*h+11]);
                u2.z = pack2(s[16*h+12], s[16*h+13]); u2.w = pack2(s[16*h+14], s[16*h+15]);
                dst[half*4 + h*2    ] = u;
                dst[half*4 + h*2 + 1] = u2;
            }
        }
    } else {
        __shared__ float ws[16*CO];
        __shared__ float bs[16];
        bool isv = grp >= 5;
        int ob = (isv ? (grp-5) : (grp-1)) * 16;
        const float* W  = isv ? vw : kw;
        const float* Bv = isv ? vb : kb;
        for (int i = tid; i < 16*CO; i += 128) ws[i] = W[ob*CO + i];
        if (tid < 16) bs[tid] = Bv[ob + tid];
        __syncthreads();

        int m = idx % NQ;
        float xv[CO];
        const float* p = xo + (size_t)b*CO*NQ + m;
        #pragma unroll
        for (int c = 0; c < CO; c++) xv[c] = p[(size_t)c*NQ];

        float s[16];
        #pragma unroll
        for (int j = 0; j < 16; j++) {
            float acc = bs[j];
            const float4* w4 = (const float4*)(ws + j*CO);
            #pragma unroll
            for (int c4 = 0; c4 < CO/4; c4++) {
                float4 w = w4[c4];
                acc = fmaf(w.x, xv[4*c4+0], acc);
                acc = fmaf(w.y, xv[4*c4+1], acc);
                acc = fmaf(w.z, xv[4*c4+2], acc);
                acc = fmaf(w.w, xv[4*c4+3], acc);
            }
            s[j] = acc;
        }
        __half* dst = (isv ? g_vh + (size_t)idx*CO : g_kh + (size_t)idx*ED) + ob;
        uint4* d4 = (uint4*)dst;
        #pragma unroll
        for (int h = 0; h < 2; h++) {
            uint4 u;
            u.x = pack2(s[8*h+0], s[8*h+1]); u.y = pack2(s[8*h+2], s[8*h+3]);
            u.z = pack2(s[8*h+4], s[8*h+5]); u.w = pack2(s[8*h+6], s[8*h+7]);
            d4[h] = u;
        }
    }
}

// ---------------------------------------------------------------------------
// Kernel 2: split-K flash attention, M=32 per warp (4 warps, 128 threads),
// 2 CTAs/SM  —  exact R9 configuration (best measured mainloop).
// ---------------------------------------------------------------------------
__global__ __launch_bounds__(128, 2) void attn_kernel(
    const float* __restrict__ ow,
    const float* __restrict__ gam, const float* __restrict__ bet,
    const float* __restrict__ mu,  const float* __restrict__ var,
    float* __restrict__ out)
{
    extern __shared__ __align__(16) char sm[];
    float* osm = (float*)(sm + SM_OSM);

    const int tid = threadIdx.x;
    const int l = tid & 31, w = tid >> 5;   // 4 warps
    const int b = blockIdx.y;
    const int z = blockIdx.z;
    const int r = b*NQB + blockIdx.x;       // qblock id

    uint32_t smb  = (uint32_t)__cvta_generic_to_shared(sm);
    uint32_t qs_b = smb + SM_Q;
    uint32_t ks_b = smb + SM_K;
    uint32_t vs_b = smb + SM_V;

    // ---- stage Q tile to smem (rows of 72 halves = 144B) ----
    {
        const uint4* qsrc = (const uint4*)(g_qh + ((size_t)b*NQ + blockIdx.x*QB)*ED);
        #pragma unroll
        for (int i = 0; i < 8; i++) {
            int c = tid + i*128;
            int row = c >> 3, c8 = c & 7;
            *(uint4*)(sm + SM_Q + row*144 + c8*16) = qsrc[row*8 + c8];
        }
    }
    __syncthreads();

    // ---- Q fragments: 2 row-halves x 4 k-steps (warp w owns rows [32w,32w+32)) ----
    uint32_t qa[2][4][4];
    {
        int colh = l >> 4;
        #pragma unroll
        for (int h = 0; h < 2; h++) {
            int row = 32*w + 16*h + (l & 15);
            #pragma unroll
            for (int kk = 0; kk < 4; kk++)
                ldsm4(qa[h][kk], qs_b + row*144 + (16*kk + 8*colh)*2);
        }
    }

    const __half* kg = g_kh + (size_t)b*NQ*ED + (size_t)z*NT2*KT*ED;
    const __half* vg = g_vh + (size_t)b*NQ*CO + (size_t)z*NT2*KT*CO;

    auto load_tile = [&](int t) {
        int buf = t & (NBUF-1);
        #pragma unroll
        for (int i = 0; i < 4; i++) {
            int c = tid + i*128;
            int row = c >> 3, c8 = c & 7;
            cpasync16(ks_b + buf*9216 + row*144 + c8*16,
                      kg + (size_t)(t*KT + row)*ED + c8*8);
        }
        #pragma unroll
        for (int i = 0; i < 2; i++) {
            int c = tid + i*128;
            int row = c >> 2, c4 = c & 3;
            cpasync16(vs_b + buf*5120 + row*80 + c4*16,
                      vg + (size_t)(t*KT + row)*CO + c4*8);
        }
        cp_commit();
    };

    const uint32_t k_lane = (uint32_t)((8*(l >> 4) + (l & 7))*144 + ((l & 15) >> 3)*16);
    const int vqd = l >> 3;
    const uint32_t v_lane = (uint32_t)(((vqd & 1)*8 + (l & 7))*80 + (vqd >> 1)*16);

    float oacc[2][4][4];
    #pragma unroll
    for (int h = 0; h < 2; h++)
        #pragma unroll
        for (int ot = 0; ot < 4; ot++)
            #pragma unroll
            for (int rr = 0; rr < 4; rr++) oacc[h][ot][rr] = 0.f;
    float dacc[2][4] = {{0.f,0.f,0.f,0.f},{0.f,0.f,0.f,0.f}};
    const uint32_t bones[2] = { ONES2, ONES2 };

    load_tile(0);
    load_tile(1);

    for (int t = 0; t < NT2; t++) {
        if (t + 2 < NT2) { load_tile(t + 2); cp_waitg(2); }
        else if (t + 1 < NT2) cp_waitg(1);
        else cp_waitg(0);
        __syncthreads();

        int buf = t & (NBUF-1);
        uint32_t kbase = ks_b + buf*9216 + k_lane;
        uint32_t vbase = vs_b + buf*5120 + v_lane;

        // sc[h][j][2] : S f16 accumulators; overwritten in place by exp2 -> P
        uint32_t sc[2][8][2];
        #pragma unroll
        for (int h = 0; h < 2; h++)
            #pragma unroll
            for (int j = 0; j < 8; j++) { sc[h][j][0] = 0u; sc[h][j][1] = 0u; }

        // ---- S, keys 0..31: each kb fragment feeds both row-halves ----
        #pragma unroll
        for (int kk = 0; kk < 4; kk++) {
            uint32_t kb[8];
            ldsm4(&kb[0], kbase + 0*2304 + kk*32);
            ldsm4(&kb[4], kbase + 1*2304 + kk*32);
            #pragma unroll
            for (int j = 0; j < 4; j++) {
                mma16816h(sc[0][j], qa[0][kk], &kb[2*j]);
                mma16816h(sc[1][j], qa[1][kk], &kb[2*j]);
            }
        }
        // ex2 keys 0..31
        #pragma unroll
        for (int h = 0; h < 2; h++)
            #pragma unroll
            for (int j = 0; j < 4; j++) {
                sc[h][j][0] = h2ex2(sc[h][j][0]);
                sc[h][j][1] = h2ex2(sc[h][j][1]);
            }
        // ---- S, keys 32..63 — fills tensor pipe during ex2 above ----
        #pragma unroll
        for (int kk = 0; kk < 4; kk++) {
            uint32_t kb[8];
            ldsm4(&kb[0], kbase + 2*2304 + kk*32);
            ldsm4(&kb[4], kbase + 3*2304 + kk*32);
            #pragma unroll
            for (int j = 0; j < 4; j++) {
                mma16816h(sc[0][4+j], qa[0][kk], &kb[2*j]);
                mma16816h(sc[1][4+j], qa[1][kk], &kb[2*j]);
            }
        }
        // ---- PV, keys 0..31 ----
        #pragma unroll
        for (int kk2 = 0; kk2 < 2; kk2++) {
            uint32_t vb[8];
            ldsm4t(&vb[0], vbase + kk2*1280);
            ldsm4t(&vb[4], vbase + kk2*1280 + 32);
            #pragma unroll
            for (int h = 0; h < 2; h++) {
                uint32_t paH[4] = { sc[h][2*kk2][0], sc[h][2*kk2][1],
                                    sc[h][2*kk2+1][0], sc[h][2*kk2+1][1] };
                #pragma unroll
                for (int ot = 0; ot < 4; ot++)
                    mma16816(oacc[h][ot], paH, &vb[2*ot]);
                mma16816(dacc[h], paH, bones);
            }
        }
        // ex2 keys 32..63
        #pragma unroll
        for (int h = 0; h < 2; h++)
            #pragma unroll
            for (int j = 4; j < 8; j++) {
                sc[h][j][0] = h2ex2(sc[h][j][0]);
                sc[h][j][1] = h2ex2(sc[h][j][1]);
            }
        // ---- PV, keys 32..63 ----
        #pragma unroll
        for (int kk2 = 2; kk2 < 4; kk2++) {
            uint32_t vb[8];
            ldsm4t(&vb[0], vbase + kk2*1280);
            ldsm4t(&vb[4], vbase + kk2*1280 + 32);
            #pragma unroll
            for (int h = 0; h < 2; h++) {
                uint32_t paH[4] = { sc[h][2*kk2][0], sc[h][2*kk2][1],
                                    sc[h][2*kk2+1][0], sc[h][2*kk2+1][1] };
                #pragma unroll
                for (int ot = 0; ot < 4; ot++)
                    mma16816(oacc[h][ot], paH, &vb[2*ot]);
                mma16816(dacc[h], paH, bones);
            }
        }
    }

    // ---- stage unnormalized partials (num[32] + den) into smem ----
    __syncthreads();
    {
        int g = l >> 2, tig = l & 3;
        #pragma unroll
        for (int h = 0; h < 2; h++) {
            int r0 = 32*w + 16*h + g, r1 = r0 + 8;
            #pragma unroll
            for (int ot = 0; ot < 4; ot++) {
                osm[r0*PSTRIDE + 8*ot + 2*tig    ] = oacc[h][ot][0];
                osm[r0*PSTRIDE + 8*ot + 2*tig + 1] = oacc[h][ot][1];
                osm[r1*PSTRIDE + 8*ot + 2*tig    ] = oacc[h][ot][2];
                osm[r1*PSTRIDE + 8*ot + 2*tig + 1] = oacc[h][ot][3];
            }
            if (tig == 0) {
                osm[r0*PSTRIDE + 32] = dacc[h][0];
                osm[r1*PSTRIDE + 32] = dacc[h][2];
            }
        }
    }
    __syncthreads();

    // ---- publish partial; second CTA of the split pair combines ----
    {
        float* dst = g_part + (size_t)(z*BATCH*NQB + r) * (QB*PSTRIDE);
        #pragma unroll
        for (int i = 0; i < (QB*PSTRIDE)/128; i++)
            dst[tid + i*128] = osm[tid + i*128];
    }
    __threadfence();
    __syncthreads();

    __shared__ int s_flag;
    if (tid == 0) {
        int old = atomicAdd(&g_sync[r], 1);
        s_flag = old;
        if (old == 1) atomicExch(&g_sync[r], 0);   // reset for graph replay
    }
    __syncthreads();
    if (s_flag == 0) return;
    __threadfence();

    // ---- consumer: combine both partials, conv+BN+ReLU ----
    float* wsm = (float*)(sm + SM_WSM);
    float* bna = (float*)(sm + SM_BNA);
    float* bnb = (float*)(sm + SM_BNB);
    for (int i = tid; i < CT*CO; i += 128) wsm[i] = ow[i];
    if (tid < CT) {
        float a = gam[tid] * rsqrtf(var[tid] + 1e-5f);
        bna[tid] = a;
        bnb[tid] = bet[tid] - mu[tid]*a;
    }
    __syncthreads();

    {
        int q = tid;
        const float* p0 = g_part + (size_t)r * (QB*PSTRIDE) + q*PSTRIDE;
        const float* p1 = p0 + (size_t)BATCH*NQB*QB*PSTRIDE;

        float den = __ldcg(p0 + 32) + __ldcg(p1 + 32);
        float inv = 1.0f / den;
        float a[CO];
        #pragma unroll
        for (int o4 = 0; o4 < CO/4; o4++) {
            float4 u = __ldcg((const float4*)p0 + o4);
            float4 v = __ldcg((const float4*)p1 + o4);
            a[4*o4+0] = (u.x + v.x) * inv;
            a[4*o4+1] = (u.y + v.y) * inv;
            a[4*o4+2] = (u.z + v.z) * inv;
            a[4*o4+3] = (u.w + v.w) * inv;
        }

        float* op = out + (size_t)b*CT*NQ + blockIdx.x*QB + q;
        #pragma unroll 4
        for (int ct = 0; ct < CT; ct++) {
            float g = 0.f;
            const float4* w4 = (const float4*)(wsm + ct*CO);
            #pragma unroll
            for (int o4 = 0; o4 < CO/4; o4++) {
                float4 wv = w4[o4];
                g = fmaf(wv.x, a[4*o4+0], g);
                g = fmaf(wv.y, a[4*o4+1], g);
                g = fmaf(wv.z, a[4*o4+2], g);
                g = fmaf(wv.w, a[4*o4+3], g);
            }
            g = fmaf(g, bna[ct], bnb[ct]);
            op[(size_t)ct*NQ] = fmaxf(g, 0.f);
        }
    }
}

// ---------------------------------------------------------------------------
extern "C" void kernel_launch(void* const* d_in, const int* in_sizes, int n_in,
                              void* d_out, int out_size)
{
    const float* xt  = (const float*)d_in[0];
    const float* xo  = (const float*)d_in[1];
    const float* qw  = (const float*)d_in[2];
    const float* qb  = (const float*)d_in[3];
    const float* kw  = (const float*)d_in[4];
    const float* kb  = (const float*)d_in[5];
    const float* vw  = (const float*)d_in[6];
    const float* vb  = (const float*)d_in[7];
    const float* ow  = (const float*)d_in[8];
    const float* gam = (const float*)d_in[9];
    const float* bet = (const float*)d_in[10];
    const float* mu  = (const float*)d_in[11];
    const float* var = (const float*)d_in[12];
    float* out = (float*)d_out;

    static int smem_set = 0;
    if (!smem_set) {
        cudaFuncSetAttribute(attn_kernel,
            cudaFuncAttributeMaxDynamicSharedMemorySize, SM_TOTAL);
        smem_set = 1;
    }

    dim3 gq((BATCH*NS)/128, 4);
    proj_qsmall_kernel<<<gq, 128>>>(xt, qw, qb);
    dim3 gp((BATCH*NQ)/128, 7);
    proj_kernel<<<gp, 128>>>(xo, kw, kb, vw, vb);
    dim3 ga(NQB, BATCH, NSPLIT);
    attn_kernel<<<ga, 128, SM_TOTAL>>>(ow, gam, bet, mu, var, out);
}

// round 13
// speedup vs baseline: 1.6391x; 1.0446x over previous
#include <cuda_runtime.h>
#include <cuda_fp16.h>
#include <cstdint>
#include <math.h>

#define BATCH 2
#define CT 64      // thermal channels (= output channels)
#define CO 32      // optical channels (= V dim)
#define ED 64      // embed dim E
#define HI 32
#define WI 32
#define HO 96
#define WO 96
#define NQ (HO*WO)     // 9216
#define NS (HI*WI)     // 1024 (small-grid pixels)
#define QB 128         // queries per CTA
#define KT 64          // keys per smem tile
#define NSPLIT 2       // key-dimension split
#define NT2 (NQ/KT/NSPLIT)   // 72 tiles per CTA
#define NQB (NQ/QB)    // 72 query blocks
#define QSCALE 0.180336880f   // (1/sqrt(64)) * log2(e): softmax becomes exp2(s)
#define ONES2 0x3C003C00u     // f16x2 {1.0, 1.0}
#define PSTRIDE 36     // padded row: 32 num + den@32 + pad (144B, 16B aligned)
#define NBUF 4         // K/V smem ring depth

// dynamic smem layout (75776 B total) -> 2 CTAs/SM
#define SM_Q   0                      // [128][144B]
#define SM_K   18432                  // 4 x [64 rows][144B]
#define SM_V   55296                  // 4 x [64 rows][80B]
#define SM_TOTAL 75776
// epilogue overlays
#define SM_OSM 0                      // [128][36] f32
#define SM_WSM 18432                  // [64][32] f32
#define SM_BNA 26624
#define SM_BNB 26880

// scratch (allocation-free: __device__ globals)
__device__ float  g_qs[BATCH*NS*ED];   // small-grid Q (fp32, scaled+biased)
__device__ __half g_kh[BATCH*NQ*ED];   // [b][m][e]
__device__ __half g_vh[BATCH*NQ*CO];   // [b][m][o]
__device__ float  g_part[NSPLIT*BATCH*NQB*QB*PSTRIDE];  // split-K partials
__device__ int    g_sync[BATCH*NQB];   // per-qblock arrival counters

// ---------------------------------------------------------------------------
// helpers
// ---------------------------------------------------------------------------
__device__ __forceinline__ uint32_t pack2(float a, float b) {
    __half2 h = __floats2half2_rn(a, b);
    return *(uint32_t*)&h;
}
__device__ __forceinline__ uint32_t h2ex2(uint32_t x) {
    uint32_t y; asm("ex2.approx.f16x2 %0, %1;" : "=r"(y) : "r"(x)); return y;
}
__device__ __forceinline__ void ldsm4(uint32_t* r, uint32_t addr) {
    asm volatile("ldmatrix.sync.aligned.m8n8.x4.shared.b16 {%0,%1,%2,%3}, [%4];"
        : "=r"(r[0]), "=r"(r[1]), "=r"(r[2]), "=r"(r[3]) : "r"(addr));
}
__device__ __forceinline__ void ldsm4t(uint32_t* r, uint32_t addr) {
    asm volatile("ldmatrix.sync.aligned.m8n8.x4.trans.shared.b16 {%0,%1,%2,%3}, [%4];"
        : "=r"(r[0]), "=r"(r[1]), "=r"(r[2]), "=r"(r[3]) : "r"(addr));
}
__device__ __forceinline__ void mma16816(float* c, const uint32_t* a, const uint32_t* b) {
    asm volatile("mma.sync.aligned.m16n8k16.row.col.f32.f16.f16.f32 "
        "{%0,%1,%2,%3}, {%4,%5,%6,%7}, {%8,%9}, {%0,%1,%2,%3};"
        : "+f"(c[0]), "+f"(c[1]), "+f"(c[2]), "+f"(c[3])
        : "r"(a[0]), "r"(a[1]), "r"(a[2]), "r"(a[3]), "r"(b[0]), "r"(b[1]));
}
__device__ __forceinline__ void mma16816h(uint32_t* c, const uint32_t* a, const uint32_t* b) {
    asm volatile("mma.sync.aligned.m16n8k16.row.col.f16.f16.f16.f16 "
        "{%0,%1}, {%2,%3,%4,%5}, {%6,%7}, {%0,%1};"
        : "+r"(c[0]), "+r"(c[1])
        : "r"(a[0]), "r"(a[1]), "r"(a[2]), "r"(a[3]), "r"(b[0]), "r"(b[1]));
}
__device__ __forceinline__ void cpasync16(uint32_t dst, const void* src) {
    asm volatile("cp.async.cg.shared.global [%0], [%1], 16;"
        :: "r"(dst), "l"(__cvta_generic_to_global(src)));
}
__device__ __forceinline__ void cp_commit() { asm volatile("cp.async.commit_group;" ::); }
__device__ __forceinline__ void cp_waitg(int n) {
    if (n == 0) asm volatile("cp.async.wait_group 0;" ::: "memory");
    else if (n == 1) asm volatile("cp.async.wait_group 1;" ::: "memory");
    else asm volatile("cp.async.wait_group 2;" ::: "memory");
}

// ---------------------------------------------------------------------------
// Kernel 1 (merged): grid (144, 7); grid.y selects work group
//   y 0..3 : K  (16 e-outputs per group)
//   y 4..5 : V  (16 o-outputs per group)
//   y 6    : Q small-grid conv (commutes with upsample); 128 active CTAs,
//            1 pixel/thread x 8 e-outputs, bias+QSCALE folded, fp32 out.
// ---------------------------------------------------------------------------
__global__ __launch_bounds__(128) void proj_kernel(
    const float* __restrict__ xt, const float* __restrict__ xo,
    const float* __restrict__ qw, const float* __restrict__ qb,
    const float* __restrict__ kw, const float* __restrict__ kb,
    const float* __restrict__ vw, const float* __restrict__ vb)
{
    __shared__ float ws[16*CO];
    __shared__ float bs[16];
    __shared__ float wq[8*CT];
    const int tid = threadIdx.x;
    const int grp = blockIdx.y;

    if (grp < 6) {
        const int idx = blockIdx.x*128 + tid;     // B*NQ threads
        const int b = idx / NQ;
        bool isv = grp >= 4;
        int ob = (isv ? (grp-4) : grp) * 16;
        const float* W  = isv ? vw : kw;
        const float* Bv = isv ? vb : kb;
        for (int i = tid; i < 16*CO; i += 128) ws[i] = W[ob*CO + i];
        if (tid < 16) bs[tid] = Bv[ob + tid];
        __syncthreads();

        int m = idx % NQ;
        float xv[CO];
        const float* p = xo + (size_t)b*CO*NQ + m;
        #pragma unroll
        for (int c = 0; c < CO; c++) xv[c] = p[(size_t)c*NQ];

        float s[16];
        #pragma unroll
        for (int j = 0; j < 16; j++) {
            float acc = bs[j];
            const float4* w4 = (const float4*)(ws + j*CO);
            #pragma unroll
            for (int c4 = 0; c4 < CO/4; c4++) {
                float4 w = w4[c4];
                acc = fmaf(w.x, xv[4*c4+0], acc);
                acc = fmaf(w.y, xv[4*c4+1], acc);
                acc = fmaf(w.z, xv[4*c4+2], acc);
                acc = fmaf(w.w, xv[4*c4+3], acc);
            }
            s[j] = acc;
        }
        __half* dst = (isv ? g_vh + (size_t)idx*CO : g_kh + (size_t)idx*ED) + ob;
        uint4* d4 = (uint4*)dst;
        #pragma unroll
        for (int h = 0; h < 2; h++) {
            uint4 u;
            u.x = pack2(s[8*h+0], s[8*h+1]); u.y = pack2(s[8*h+2], s[8*h+3]);
            u.z = pack2(s[8*h+4], s[8*h+5]); u.w = pack2(s[8*h+6], s[8*h+7]);
            d4[h] = u;
        }
    } else {
        // ---- Q small-grid conv: CTA bx covers pixels (bx&15)*128+tid,
        //      e-outputs [(bx>>4)*8, +8). CTAs 128..143 idle. ----
        if (blockIdx.x >= 128) return;
        const int eb = (blockIdx.x >> 4) * 8;
        const int px = (blockIdx.x & 15)*128 + tid;   // 0..2047 = b*NS+n
        for (int i = tid; i < 8*CT; i += 128) wq[i] = qw[eb*CT + i] * QSCALE;
        __shared__ float bq[8];
        if (tid < 8) bq[tid] = qb[eb + tid] * QSCALE;
        __syncthreads();

        const int b2 = px / NS, n2 = px % NS;
        float xv[CT];
        const float* p = xt + (size_t)b2*CT*NS + n2;
        #pragma unroll
        for (int c = 0; c < CT; c++) xv[c] = p[(size_t)c*NS];

        float* dst = g_qs + (size_t)px*ED + eb;
        #pragma unroll
        for (int j = 0; j < 8; j++) {
            float acc = bq[j];
            const float4* w4 = (const float4*)(wq + j*CT);
            #pragma unroll
            for (int c4 = 0; c4 < CT/4; c4++) {
                float4 w = w4[c4];
                acc = fmaf(w.x, xv[4*c4+0], acc);
                acc = fmaf(w.y, xv[4*c4+1], acc);
                acc = fmaf(w.z, xv[4*c4+2], acc);
                acc = fmaf(w.w, xv[4*c4+3], acc);
            }
            dst[j] = acc;
        }
    }
}

// ---------------------------------------------------------------------------
// Kernel 2: split-K flash attention, M=32 per warp (4 warps, 128 threads),
// 2 CTAs/SM — R9 mainloop. Prologue performs the bilinear Q upsample
// directly from fp32 g_qs into the smem Q tile (no g_qh round-trip).
// ---------------------------------------------------------------------------
__global__ __launch_bounds__(128, 2) void attn_kernel(
    const float* __restrict__ ow,
    const float* __restrict__ gam, const float* __restrict__ bet,
    const float* __restrict__ mu,  const float* __restrict__ var,
    float* __restrict__ out)
{
    extern __shared__ __align__(16) char sm[];
    float* osm = (float*)(sm + SM_OSM);

    const int tid = threadIdx.x;
    const int l = tid & 31, w = tid >> 5;   // 4 warps
    const int b = blockIdx.y;
    const int z = blockIdx.z;
    const int r = b*NQB + blockIdx.x;       // qblock id

    uint32_t smb  = (uint32_t)__cvta_generic_to_shared(sm);
    uint32_t qs_b = smb + SM_Q;
    uint32_t ks_b = smb + SM_K;
    uint32_t vs_b = smb + SM_V;

    const __half* kg = g_kh + (size_t)b*NQ*ED + (size_t)z*NT2*KT*ED;
    const __half* vg = g_vh + (size_t)b*NQ*CO + (size_t)z*NT2*KT*CO;

    auto load_tile = [&](int t) {
        int buf = t & (NBUF-1);
        #pragma unroll
        for (int i = 0; i < 4; i++) {
            int c = tid + i*128;
            int row = c >> 3, c8 = c & 7;
            cpasync16(ks_b + buf*9216 + row*144 + c8*16,
                      kg + (size_t)(t*KT + row)*ED + c8*8);
        }
        #pragma unroll
        for (int i = 0; i < 2; i++) {
            int c = tid + i*128;
            int row = c >> 2, c4 = c & 3;
            cpasync16(vs_b + buf*5120 + row*80 + c4*16,
                      vg + (size_t)(t*KT + row)*CO + c4*8);
        }
        cp_commit();
    };

    // start the K/V pipeline before the Q prologue so it overlaps
    load_tile(0);
    load_tile(1);

    // ---- prologue: bilinear upsample of projected Q into smem (1 row/thread) ----
    {
        int n = blockIdx.x*QB + tid;
        int y = n / WO, x = n % WO;
        float sy = (y + 0.5f) * (1.0f/3.0f) - 0.5f;
        float sx = (x + 0.5f) * (1.0f/3.0f) - 0.5f;
        float fy0 = floorf(sy), fx0 = floorf(sx);
        float fy = sy - fy0, fx = sx - fx0;
        int y0 = (int)fy0, x0 = (int)fx0;
        int y0c = max(y0, 0), y1c = min(y0+1, HI-1);
        int x0c = max(x0, 0), x1c = min(x0+1, WI-1);
        float w00 = (1.f-fy)*(1.f-fx), w01 = (1.f-fy)*fx;
        float w10 = fy*(1.f-fx),       w11 = fy*fx;

        const float4* t00 = (const float4*)(g_qs + ((size_t)b*NS + y0c*WI + x0c)*ED);
        const float4* t01 = (const float4*)(g_qs + ((size_t)b*NS + y0c*WI + x1c)*ED);
        const float4* t10 = (const float4*)(g_qs + ((size_t)b*NS + y1c*WI + x0c)*ED);
        const float4* t11 = (const float4*)(g_qs + ((size_t)b*NS + y1c*WI + x1c)*ED);

        char* rowp = sm + SM_Q + tid*144;
        #pragma unroll
        for (int i = 0; i < 16; i += 2) {
            float4 a0 = t00[i],   a1 = t00[i+1];
            float4 c0 = t01[i],   c1 = t01[i+1];
            float4 d0 = t10[i],   d1 = t10[i+1];
            float4 e0 = t11[i],   e1 = t11[i+1];
            float s0 = w00*a0.x + w01*c0.x + w10*d0.x + w11*e0.x;
            float s1 = w00*a0.y + w01*c0.y + w10*d0.y + w11*e0.y;
            float s2 = w00*a0.z + w01*c0.z + w10*d0.z + w11*e0.z;
            float s3 = w00*a0.w + w01*c0.w + w10*d0.w + w11*e0.w;
            float s4 = w00*a1.x + w01*c1.x + w10*d1.x + w11*e1.x;
            float s5 = w00*a1.y + w01*c1.y + w10*d1.y + w11*e1.y;
            float s6 = w00*a1.z + w01*c1.z + w10*d1.z + w11*e1.z;
            float s7 = w00*a1.w + w01*c1.w + w10*d1.w + w11*e1.w;
            uint4 u;
            u.x = pack2(s0, s1); u.y = pack2(s2, s3);
            u.z = pack2(s4, s5); u.w = pack2(s6, s7);
            *(uint4*)(rowp + (i/2)*16) = u;
        }
    }
    __syncthreads();

    // ---- Q fragments: 2 row-halves x 4 k-steps (warp w owns rows [32w,32w+32)) ----
    uint32_t qa[2][4][4];
    {
        int colh = l >> 4;
        #pragma unroll
        for (int h = 0; h < 2; h++) {
            int row = 32*w + 16*h + (l & 15);
            #pragma unroll
            for (int kk = 0; kk < 4; kk++)
                ldsm4(qa[h][kk], qs_b + row*144 + (16*kk + 8*colh)*2);
        }
    }

    const uint32_t k_lane = (uint32_t)((8*(l >> 4) + (l & 7))*144 + ((l & 15) >> 3)*16);
    const int vqd = l >> 3;
    const uint32_t v_lane = (uint32_t)(((vqd & 1)*8 + (l & 7))*80 + (vqd >> 1)*16);

    float oacc[2][4][4];
    #pragma unroll
    for (int h = 0; h < 2; h++)
        #pragma unroll
        for (int ot = 0; ot < 4; ot++)
            #pragma unroll
            for (int rr = 0; rr < 4; rr++) oacc[h][ot][rr] = 0.f;
    float dacc[2][4] = {{0.f,0.f,0.f,0.f},{0.f,0.f,0.f,0.f}};
    const uint32_t bones[2] = { ONES2, ONES2 };

    for (int t = 0; t < NT2; t++) {
        if (t + 2 < NT2) { load_tile(t + 2); cp_waitg(2); }
        else if (t + 1 < NT2) cp_waitg(1);
        else cp_waitg(0);
        __syncthreads();

        int buf = t & (NBUF-1);
        uint32_t kbase = ks_b + buf*9216 + k_lane;
        uint32_t vbase = vs_b + buf*5120 + v_lane;

        // sc[h][j][2] : S f16 accumulators; overwritten in place by exp2 -> P
        uint32_t sc[2][8][2];
        #pragma unroll
        for (int h = 0; h < 2; h++)
            #pragma unroll
            for (int j = 0; j < 8; j++) { sc[h][j][0] = 0u; sc[h][j][1] = 0u; }

        // ---- S, keys 0..31: each kb fragment feeds both row-halves ----
        #pragma unroll
        for (int kk = 0; kk < 4; kk++) {
            uint32_t kb[8];
            ldsm4(&kb[0], kbase + 0*2304 + kk*32);
            ldsm4(&kb[4], kbase + 1*2304 + kk*32);
            #pragma unroll
            for (int j = 0; j < 4; j++) {
                mma16816h(sc[0][j], qa[0][kk], &kb[2*j]);
                mma16816h(sc[1][j], qa[1][kk], &kb[2*j]);
            }
        }
        // ex2 keys 0..31
        #pragma unroll
        for (int h = 0; h < 2; h++)
            #pragma unroll
            for (int j = 0; j < 4; j++) {
                sc[h][j][0] = h2ex2(sc[h][j][0]);
                sc[h][j][1] = h2ex2(sc[h][j][1]);
            }
        // ---- S, keys 32..63 — fills tensor pipe during ex2 above ----
        #pragma unroll
        for (int kk = 0; kk < 4; kk++) {
            uint32_t kb[8];
            ldsm4(&kb[0], kbase + 2*2304 + kk*32);
            ldsm4(&kb[4], kbase + 3*2304 + kk*32);
            #pragma unroll
            for (int j = 0; j < 4; j++) {
                mma16816h(sc[0][4+j], qa[0][kk], &kb[2*j]);
                mma16816h(sc[1][4+j], qa[1][kk], &kb[2*j]);
            }
        }
        // ---- PV, keys 0..31 ----
        #pragma unroll
        for (int kk2 = 0; kk2 < 2; kk2++) {
            uint32_t vb[8];
            ldsm4t(&vb[0], vbase + kk2*1280);
            ldsm4t(&vb[4], vbase + kk2*1280 + 32);
            #pragma unroll
            for (int h = 0; h < 2; h++) {
                uint32_t paH[4] = { sc[h][2*kk2][0], sc[h][2*kk2][1],
                                    sc[h][2*kk2+1][0], sc[h][2*kk2+1][1] };
                #pragma unroll
                for (int ot = 0; ot < 4; ot++)
                    mma16816(oacc[h][ot], paH, &vb[2*ot]);
                mma16816(dacc[h], paH, bones);
            }
        }
        // ex2 keys 32..63
        #pragma unroll
        for (int h = 0; h < 2; h++)
            #pragma unroll
            for (int j = 4; j < 8; j++) {
                sc[h][j][0] = h2ex2(sc[h][j][0]);
                sc[h][j][1] = h2ex2(sc[h][j][1]);
            }
        // ---- PV, keys 32..63 ----
        #pragma unroll
        for (int kk2 = 2; kk2 < 4; kk2++) {
            uint32_t vb[8];
            ldsm4t(&vb[0], vbase + kk2*1280);
            ldsm4t(&vb[4], vbase + kk2*1280 + 32);
            #pragma unroll
            for (int h = 0; h < 2; h++) {
                uint32_t paH[4] = { sc[h][2*kk2][0], sc[h][2*kk2][1],
                                    sc[h][2*kk2+1][0], sc[h][2*kk2+1][1] };
                #pragma unroll
                for (int ot = 0; ot < 4; ot++)
                    mma16816(oacc[h][ot], paH, &vb[2*ot]);
                mma16816(dacc[h], paH, bones);
            }
        }
    }

    // ---- stage unnormalized partials (num[32] + den) into smem ----
    __syncthreads();
    {
        int g = l >> 2, tig = l & 3;
        #pragma unroll
        for (int h = 0; h < 2; h++) {
            int r0 = 32*w + 16*h + g, r1 = r0 + 8;
            #pragma unroll
            for (int ot = 0; ot < 4; ot++) {
                osm[r0*PSTRIDE + 8*ot + 2*tig    ] = oacc[h][ot][0];
                osm[r0*PSTRIDE + 8*ot + 2*tig + 1] = oacc[h][ot][1];
                osm[r1*PSTRIDE + 8*ot + 2*tig    ] = oacc[h][ot][2];
                osm[r1*PSTRIDE + 8*ot + 2*tig + 1] = oacc[h][ot][3];
            }
            if (tig == 0) {
                osm[r0*PSTRIDE + 32] = dacc[h][0];
                osm[r1*PSTRIDE + 32] = dacc[h][2];
            }
        }
    }
    __syncthreads();

    // ---- publish partial; second CTA of the split pair combines ----
    {
        float* dst = g_part + (size_t)(z*BATCH*NQB + r) * (QB*PSTRIDE);
        #pragma unroll
        for (int i = 0; i < (QB*PSTRIDE)/128; i++)
            dst[tid + i*128] = osm[tid + i*128];
    }
    __threadfence();
    __syncthreads();

    __shared__ int s_flag;
    if (tid == 0) {
        int old = atomicAdd(&g_sync[r], 1);
        s_flag = old;
        if (old == 1) atomicExch(&g_sync[r], 0);   // reset for graph replay
    }
    __syncthreads();
    if (s_flag == 0) return;
    __threadfence();

    // ---- consumer: combine both partials, conv+BN+ReLU ----
    float* wsm = (float*)(sm + SM_WSM);
    float* bna = (float*)(sm + SM_BNA);
    float* bnb = (float*)(sm + SM_BNB);
    for (int i = tid; i < CT*CO; i += 128) wsm[i] = ow[i];
    if (tid < CT) {
        float a = gam[tid] * rsqrtf(var[tid] + 1e-5f);
        bna[tid] = a;
        bnb[tid] = bet[tid] - mu[tid]*a;
    }
    __syncthreads();

    {
        int q = tid;
        const float* p0 = g_part + (size_t)r * (QB*PSTRIDE) + q*PSTRIDE;
        const float* p1 = p0 + (size_t)BATCH*NQB*QB*PSTRIDE;

        float den = __ldcg(p0 + 32) + __ldcg(p1 + 32);
        float inv = 1.0f / den;
        float a[CO];
        #pragma unroll
        for (int o4 = 0; o4 < CO/4; o4++) {
            float4 u = __ldcg((const float4*)p0 + o4);
            float4 v = __ldcg((const float4*)p1 + o4);
            a[4*o4+0] = (u.x + v.x) * inv;
            a[4*o4+1] = (u.y + v.y) * inv;
            a[4*o4+2] = (u.z + v.z) * inv;
            a[4*o4+3] = (u.w + v.w) * inv;
        }

        float* op = out + (size_t)b*CT*NQ + blockIdx.x*QB + q;
        #pragma unroll 4
        for (int ct = 0; ct < CT; ct++) {
            float g = 0.f;
            const float4* w4 = (const float4*)(wsm + ct*CO);
            #pragma unroll
            for (int o4 = 0; o4 < CO/4; o4++) {
                float4 wv = w4[o4];
                g = fmaf(wv.x, a[4*o4+0], g);
                g = fmaf(wv.y, a[4*o4+1], g);
                g = fmaf(wv.z, a[4*o4+2], g);
                g = fmaf(wv.w, a[4*o4+3], g);
            }
            g = fmaf(g, bna[ct], bnb[ct]);
            op[(size_t)ct*NQ] = fmaxf(g, 0.f);
        }
    }
}

// ---------------------------------------------------------------------------
extern "C" void kernel_launch(void* const* d_in, const int* in_sizes, int n_in,
                              void* d_out, int out_size)
{
    const float* xt  = (const float*)d_in[0];
    const float* xo  = (const float*)d_in[1];
    const float* qw  = (const float*)d_in[2];
    const float* qb  = (const float*)d_in[3];
    const float* kw  = (const float*)d_in[4];
    const float* kb  = (const float*)d_in[5];
    const float* vw  = (const float*)d_in[6];
    const float* vb  = (const float*)d_in[7];
    const float* ow  = (const float*)d_in[8];
    const float* gam = (const float*)d_in[9];
    const float* bet = (const float*)d_in[10];
    const float* mu  = (const float*)d_in[11];
    const float* var = (const float*)d_in[12];
    float* out = (float*)d_out;

    static int smem_set = 0;
    if (!smem_set) {
        cudaFuncSetAttribute(attn_kernel,
            cudaFuncAttributeMaxDynamicSharedMemorySize, SM_TOTAL);
        smem_set = 1;
    }

    dim3 gp((BATCH*NQ)/128, 7);
    proj_kernel<<<gp, 128>>>(xt, xo, qw, qb, kw, kb, vw, vb);
    dim3 ga(NQB, BATCH, NSPLIT);
    attn_kernel<<<ga, 128, SM_TOTAL>>>(ow, gam, bet, mu, var, out);
}